// round 2
// baseline (speedup 1.0000x reference)
#include <cuda_runtime.h>

#define SS   21      // search size
#define PAD  10
#define BS   4       // block size
#define TILE 24      // BS + SS - 1
#define S2   441     // SS*SS
#define H    256
#define W    256

__global__ __launch_bounds__(128, 1)
void pred_kernel(const float* __restrict__ im1,
                 const float* __restrict__ im2,
                 float* __restrict__ out)
{
    __shared__ __align__(16) float im2t[TILE * TILE];  // 576 floats
    __shared__ float im1t[16];
    __shared__ float part[4][S2];      // per-py partial SADs
    __shared__ float wsh[S2];          // vol, then weights
    __shared__ float red[16][21];      // per-pixel partial weighted sums over i
    __shared__ float s_min[4], s_sum[4];

    const int t  = threadIdx.x;
    const int bx = blockIdx.x, by = blockIdx.y, b = blockIdx.z;
    const float* i1 = im1 + b * H * W;
    const float* i2 = im2 + b * H * W;

    // ---- Phase 0: load 24x24 im2 halo tile (zero-padded) + 4x4 im1 block ----
    const int x0 = bx * BS - PAD;
    const int y0 = by * BS - PAD;
    for (int idx = t; idx < TILE * TILE; idx += 128) {
        int r = idx / TILE, c = idx - r * TILE;
        int y = y0 + r, x = x0 + c;
        float v = 0.0f;
        if ((unsigned)y < (unsigned)H && (unsigned)x < (unsigned)W)
            v = i2[y * W + x];
        im2t[idx] = v;
    }
    if (t < 16) {
        int py = t >> 2, px = t & 3;
        im1t[t] = i1[(by * BS + py) * W + bx * BS + px];
    }
    __syncthreads();

    // ---- Phase 1: partial SADs. thread t<84 -> (i = shift row, py = pixel row)
    const int i  = t % 21;
    const int py = t / 21;
    float r[TILE];          // register-resident im2 row, reused in phase 4
    float a0 = 0.f, a1 = 0.f, a2 = 0.f, a3 = 0.f;
    if (t < 84) {
        const float4* rp = (const float4*)&im2t[(py + i) * TILE]; // 96B stride, 16B aligned
        #pragma unroll
        for (int q = 0; q < 6; q++) {
            float4 v = rp[q];
            r[q * 4 + 0] = v.x; r[q * 4 + 1] = v.y;
            r[q * 4 + 2] = v.z; r[q * 4 + 3] = v.w;
        }
        a0 = im1t[py * 4 + 0]; a1 = im1t[py * 4 + 1];
        a2 = im1t[py * 4 + 2]; a3 = im1t[py * 4 + 3];
        #pragma unroll
        for (int j = 0; j < SS; j++) {
            float pv = fabsf(a0 - r[j])     + fabsf(a1 - r[j + 1])
                     + fabsf(a2 - r[j + 2]) + fabsf(a3 - r[j + 3]);
            part[py][i * SS + j] = pv;
        }
    }
    __syncthreads();

    // ---- Phase 2: vol[k] = sum over py, find min (for softmax stability) ----
    float lmin = 1e30f;
    #pragma unroll
    for (int q = 0; q < 4; q++) {
        int k = t + q * 128;
        if (k < S2) {
            float v = part[0][k] + part[1][k] + part[2][k] + part[3][k];
            wsh[k] = v;
            lmin = fminf(lmin, v);
        }
    }
    #pragma unroll
    for (int o = 16; o; o >>= 1)
        lmin = fminf(lmin, __shfl_xor_sync(0xffffffffu, lmin, o));
    if ((t & 31) == 0) s_min[t >> 5] = lmin;
    __syncthreads();
    const float vmin = fminf(fminf(s_min[0], s_min[1]), fminf(s_min[2], s_min[3]));

    // ---- Phase 3: weights w = exp(-100 * (sum/16 - min/16)) = exp(-6.25*(sum-min))
    float lsum = 0.0f;
    #pragma unroll
    for (int q = 0; q < 4; q++) {
        int k = t + q * 128;
        if (k < S2) {
            float wv = __expf(-6.25f * (wsh[k] - vmin));
            wsh[k] = wv;            // each k owned by exactly one thread
            lsum += wv;
        }
    }
    #pragma unroll
    for (int o = 16; o; o >>= 1)
        lsum += __shfl_xor_sync(0xffffffffu, lsum, o);
    if ((t & 31) == 0) s_sum[t >> 5] = lsum;
    __syncthreads();
    const float wsum = s_sum[0] + s_sum[1] + s_sum[2] + s_sum[3];

    // ---- Phase 4: weighted accumulation, reusing register row r[] ----
    if (t < 84) {
        float acc0 = 0.f, acc1 = 0.f, acc2 = 0.f, acc3 = 0.f;
        #pragma unroll
        for (int j = 0; j < SS; j++) {
            float wj = wsh[i * SS + j];
            acc0 += wj * r[j];
            acc1 += wj * r[j + 1];
            acc2 += wj * r[j + 2];
            acc3 += wj * r[j + 3];
        }
        red[py * 4 + 0][i] = acc0;
        red[py * 4 + 1][i] = acc1;
        red[py * 4 + 2][i] = acc2;
        red[py * 4 + 3][i] = acc3;
    }
    __syncthreads();

    // ---- Phase 5: reduce over 21 shift-rows, normalize, store ----
    if (t < 16) {
        float s = 0.0f;
        #pragma unroll
        for (int q = 0; q < 21; q++) s += red[t][q];
        int py2 = t >> 2, px2 = t & 3;
        out[b * H * W + (by * BS + py2) * W + bx * BS + px2] = s / wsum;
    }
}

extern "C" void kernel_launch(void* const* d_in, const int* in_sizes, int n_in,
                              void* d_out, int out_size) {
    const float* im1 = (const float*)d_in[0];
    const float* im2 = (const float*)d_in[1];
    float* out = (float*)d_out;
    dim3 grid(W / BS, H / BS, 2);   // (64, 64, 2)
    pred_kernel<<<grid, 128>>>(im1, im2, out);
}

// round 3
// speedup vs baseline: 1.2624x; 1.2624x over previous
#include <cuda_runtime.h>

#define SS   21      // search size
#define PAD  10
#define BS   4       // block size
#define TILE 24      // BS + SS - 1
#define TP   28      // tile pitch in floats (112B: 16B-aligned, bank-conflict-friendly)
#define S2   441
#define H    256
#define W    256

__global__ __launch_bounds__(96)
void pred_kernel(const float* __restrict__ im1,
                 const float* __restrict__ im2,
                 float* __restrict__ out)
{
    __shared__ __align__(16) float im2t[TILE * TP];  // 24 rows x 28 pitch
    __shared__ float im1t[16];
    __shared__ float red[16][21];   // per-pixel partial weighted sums over i
    __shared__ float sg[21];        // per-i group min, then per-i group weight-sum
    __shared__ float s_min;

    const int t  = threadIdx.x;
    const int bx = blockIdx.x, by = blockIdx.y, b = blockIdx.z;
    const float* i1 = im1 + b * H * W;
    const float* i2 = im2 + b * H * W;

    // ---- Phase 0: load 24x24 im2 halo tile (zero-padded), pitch 28 ----
    const int x0 = bx * BS - PAD;
    const int y0 = by * BS - PAD;
    #pragma unroll
    for (int q = 0; q < 6; q++) {               // 576 / 96 = 6 exact
        int idx = t + q * 96;
        int r = idx / TILE, c = idx - r * TILE;
        int y = y0 + r, x = x0 + c;
        float v = 0.0f;
        if ((unsigned)y < (unsigned)H && (unsigned)x < (unsigned)W)
            v = i2[y * W + x];
        im2t[r * TP + c] = v;
    }
    if (t < 16) {
        int py = t >> 2, px = t & 3;
        im1t[t] = i1[(by * BS + py) * W + bx * BS + px];
    }
    __syncthreads();

    // ---- thread mapping: t = 4*i + py  (py in adjacent lanes => cheap shuffles)
    const int i  = t >> 2;          // shift row 0..20
    const int py = t & 3;           // pixel row 0..3
    const bool act = (t < 84);
    // warp 2 has only lanes 0..19 active; warps 0/1 are full
    const unsigned gmask = (t >= 64) ? 0x000FFFFFu : 0xFFFFFFFFu;

    float r[TILE];                  // register-resident im2 row (py+i), reused in phase 3
    float vol[SS];

    if (act) {
        // load 24-float row as 6x LDS.128 (pitch 112B => <=2-way conflicts)
        const float4* rp = (const float4*)&im2t[(py + i) * TP];
        #pragma unroll
        for (int q = 0; q < 6; q++) {
            float4 v = rp[q];
            r[q * 4 + 0] = v.x; r[q * 4 + 1] = v.y;
            r[q * 4 + 2] = v.z; r[q * 4 + 3] = v.w;
        }
        const float a0 = im1t[py * 4 + 0], a1 = im1t[py * 4 + 1];
        const float a2 = im1t[py * 4 + 2], a3 = im1t[py * 4 + 3];

        // per-(i,py) partial SADs for all 21 j
        #pragma unroll
        for (int j = 0; j < SS; j++) {
            vol[j] = fabsf(a0 - r[j])     + fabsf(a1 - r[j + 1])
                   + fabsf(a2 - r[j + 2]) + fabsf(a3 - r[j + 3]);
        }
        // reduce over py within the 4-lane group: every lane ends with full vol
        #pragma unroll
        for (int j = 0; j < SS; j++) {
            vol[j] += __shfl_xor_sync(gmask, vol[j], 1);
            vol[j] += __shfl_xor_sync(gmask, vol[j], 2);
        }
        // group min over j
        float lmin = vol[0];
        #pragma unroll
        for (int j = 1; j < SS; j++) lmin = fminf(lmin, vol[j]);
        if (py == 0) sg[i] = lmin;
    }
    __syncthreads();

    // ---- second-level min over 21 rows (warp 0) ----
    if (t < 32) {
        float v = (t < SS) ? sg[t] : 1e30f;
        #pragma unroll
        for (int o = 16; o; o >>= 1)
            v = fminf(v, __shfl_xor_sync(0xffffffffu, v, o));
        if (t == 0) s_min = v;
    }
    __syncthreads();

    // ---- Phase 3: fused weights + weighted accumulation (all in registers) ----
    if (act) {
        const float vmin = s_min;
        float lsum = 0.0f;
        float acc0 = 0.f, acc1 = 0.f, acc2 = 0.f, acc3 = 0.f;
        #pragma unroll
        for (int j = 0; j < SS; j++) {
            // exp(-100*(vol/16 - min/16)) = exp(-6.25*(vol - min))
            float wv = __expf(-6.25f * (vol[j] - vmin));
            lsum += wv;
            acc0 += wv * r[j];
            acc1 += wv * r[j + 1];
            acc2 += wv * r[j + 2];
            acc3 += wv * r[j + 3];
        }
        if (py == 0) sg[i] = lsum;   // safe: previous sg reads drained by last barrier
        red[py * 4 + 0][i] = acc0;
        red[py * 4 + 1][i] = acc1;
        red[py * 4 + 2][i] = acc2;
        red[py * 4 + 3][i] = acc3;
    }
    __syncthreads();

    // ---- Phase 4: reduce over 21 shift-rows, normalize, store ----
    if (t < 16) {
        float s = 0.0f;
        #pragma unroll
        for (int q = 0; q < SS; q++) s += red[t][q];   // 21t mod 32 distinct: conflict-free
        float ws = 0.0f;
        #pragma unroll
        for (int q = 0; q < SS; q++) ws += sg[q];      // broadcast reads
        int py2 = t >> 2, px2 = t & 3;
        out[b * H * W + (by * BS + py2) * W + bx * BS + px2] = s / ws;
    }
}

extern "C" void kernel_launch(void* const* d_in, const int* in_sizes, int n_in,
                              void* d_out, int out_size) {
    const float* im1 = (const float*)d_in[0];
    const float* im2 = (const float*)d_in[1];
    float* out = (float*)d_out;
    dim3 grid(W / BS, H / BS, 2);   // (64, 64, 2)
    pred_kernel<<<grid, 96>>>(im1, im2, out);
}